// round 17
// baseline (speedup 1.0000x reference)
#include <cuda_runtime.h>
#include <cuda_fp16.h>
#include <cuda_bf16.h>
#include <cstdint>

#define NN 50000
#define EE 800000
#define IN_CH 256
#define HID 128
#define LAT 64
#define NB_SCAN ((NN + 255) / 256)   // 196

// ---------------- scratch (device globals; no allocation allowed) -------------
__device__ int      g_anynz;
__device__ int      g_cnt[NN];
__device__ int2     g_sc[NN];              // (start, cnt) packed
__device__ int      g_rank[EE];            // per-edge rank within its dst bucket
__device__ unsigned g_scan_pack[NB_SCAN];  // bits31-30: 0=none,1=agg,2=incl
__device__ unsigned g_scan_ctr;
__device__ int      g_csr_src[EE];
__device__ float    g_dinv[NN];
__device__ __half2  g_h1h[(size_t)NN * (HID / 2)];
__device__ __half2  g_h2h[(size_t)NN * (LAT / 2)];

// ---------------- reset + dtype probe (fused) ---------------------------------
__global__ void k_reset_detect(const int* __restrict__ ei32, int* cnt, int n, int e,
                               int nblk) {
    int i = blockIdx.x * blockDim.x + threadIdx.x;
    if (i == 0) { g_anynz = 0; g_scan_ctr = 0; }
    if (i < n) cnt[i] = 0;
    if (i < nblk) g_scan_pack[i] = 0;
    if (i < 1024) {
        long long k = (long long)i * (e / 1024);
        if (ei32[2 * k + 1] != 0) atomicOr(&g_anynz, 1);
    }
}

// histogram + per-edge bucket rank; 2 independent edges per thread (ILP)
__global__ void k_hist_rank(const int* __restrict__ ei32, int* cnt, int* rank, int e) {
    int h = (e + 1) >> 1;
    int i = blockIdx.x * blockDim.x + threadIdx.x;
    if (i >= h) return;
    bool has1 = (i + h) < e;
    int d0, d1 = 0;
    if (g_anynz == 0) {
        d0 = ((const int2*)ei32)[(size_t)e + i].x;
        if (has1) d1 = ((const int2*)ei32)[(size_t)e + i + h].x;
    } else {
        d0 = ei32[e + i];
        if (has1) d1 = ei32[e + i + h];
    }
    rank[i] = atomicAdd(&cnt[d0], 1);
    if (has1) rank[i + h] = atomicAdd(&cnt[d1], 1);
}

// ---------------- single-pass decoupled-lookback scan --------------------------
__global__ void __launch_bounds__(256) k_scan_lookback(
    const int* __restrict__ cnt, int2* sc, float* dinv, int n)
{
    __shared__ int s[256];
    __shared__ int sbid;
    __shared__ int sprefix;
    const int tid = threadIdx.x;
    if (tid == 0) sbid = (int)atomicAdd(&g_scan_ctr, 1u);
    __syncthreads();
    const int bid = sbid;
    const int i = bid * 256 + tid;
    const int v = (i < n) ? cnt[i] : 0;

    s[tid] = v;
    __syncthreads();
    for (int off = 1; off < 256; off <<= 1) {
        int t = (tid >= off) ? s[tid - off] : 0;
        __syncthreads();
        s[tid] += t;
        __syncthreads();
    }
    const int total = s[255];

    if (tid == 0) {
        unsigned st = (bid == 0) ? 2u : 1u;
        atomicExch(&g_scan_pack[bid], (st << 30) | (unsigned)total);
    }

    if (tid < 32) {
        int prefix = 0;
        if (bid > 0) {
            int j = bid - 1;
            bool done = false;
            while (!done) {
                int idx = j - tid;
                unsigned p;
                if (idx >= 0) {
                    do { p = *(volatile unsigned*)&g_scan_pack[idx]; } while ((p >> 30) == 0u);
                } else {
                    p = (2u << 30);
                }
                unsigned stt = p >> 30;
                int val = (int)(p & 0x3FFFFFFFu);
                unsigned incl_mask = __ballot_sync(0xFFFFFFFFu, stt == 2u);
                int firstIncl = __ffs(incl_mask) - 1;
                int contrib;
                if (firstIncl >= 0) {
                    contrib = (tid <= firstIncl) ? val : 0;
                    done = true;
                } else {
                    contrib = (idx >= 0) ? val : 0;
                    j -= 32;
                }
#pragma unroll
                for (int o = 16; o; o >>= 1) contrib += __shfl_down_sync(0xFFFFFFFFu, contrib, o);
                prefix += __shfl_sync(0xFFFFFFFFu, contrib, 0);
            }
        }
        if (tid == 0) {
            sprefix = prefix;
            if (bid > 0)
                atomicExch(&g_scan_pack[bid], (2u << 30) | (unsigned)(prefix + total));
        }
    }
    __syncthreads();

    if (i < n) {
        sc[i] = make_int2(sprefix + s[tid] - v, v);
        dinv[i] = rsqrtf((float)(v + 1));
    }
}

// atomic-free bucket fill; 2 independent edges per thread (ILP)
__global__ void k_fill_rank(const int* __restrict__ ei32, const int2* __restrict__ sc,
                            const int* __restrict__ rank, int* csr, int e) {
    int h = (e + 1) >> 1;
    int i = blockIdx.x * blockDim.x + threadIdx.x;
    if (i >= h) return;
    bool has1 = (i + h) < e;
    int s0, d0, s1 = 0, d1 = 0;
    if (g_anynz == 0) {            // int64: lo words
        s0 = ((const int2*)ei32)[i].x;
        d0 = ((const int2*)ei32)[(size_t)e + i].x;
        if (has1) {
            s1 = ((const int2*)ei32)[i + h].x;
            d1 = ((const int2*)ei32)[(size_t)e + i + h].x;
        }
    } else {
        s0 = ei32[i];
        d0 = ei32[e + i];
        if (has1) { s1 = ei32[i + h]; d1 = ei32[e + i + h]; }
    }
    int r0 = rank[i];
    int p0 = sc[d0].x + r0;
    if (has1) {
        int r1 = rank[i + h];
        int p1 = sc[d1].x + r1;
        csr[p1] = s1;
    }
    csr[p0] = s0;
}

// ---------------- fp16 MMA helper ---------------------------------------------
__device__ __forceinline__ void mma_f16(float4& d,
                                        uint32_t a0, uint32_t a1, uint32_t a2, uint32_t a3,
                                        uint32_t b0, uint32_t b1) {
    asm volatile(
        "mma.sync.aligned.m16n8k16.row.col.f32.f16.f16.f32 "
        "{%0,%1,%2,%3}, {%4,%5,%6,%7}, {%8,%9}, {%0,%1,%2,%3};"
        : "+f"(d.x), "+f"(d.y), "+f"(d.z), "+f"(d.w)
        : "r"(a0), "r"(a1), "r"(a2), "r"(a3), "r"(b0), "r"(b1));
}

// ---------------- GEMM1: fp32 in -> fp16 MMA -> fp16 out, [M,256]@[256,128] ---
__global__ void __launch_bounds__(256) gemm1_f16(
    const float* __restrict__ A, const float* __restrict__ B,
    __half2* __restrict__ Ch, int M, int K)   // K=256, N=128
{
    constexpr int BM = 128, BK = 32, BN = 128;
    constexpr int NT = BN / 16;              // 8 n8-tiles per warp
    __shared__ __half As[BM][BK + 8];
    __shared__ __half Bs[BK][BN + 8];

    const int tid    = threadIdx.x;
    const int warp   = tid >> 5;
    const int lane   = tid & 31;
    const int warp_m = warp & 3;
    const int warp_n = warp >> 2;
    const int m0     = blockIdx.x * BM;
    const int qr     = lane >> 2;
    const int qc     = lane & 3;

    const int am  = tid >> 3;
    const int ak4 = (tid & 7) << 2;
    const int bk  = tid >> 5;
    const int bn4 = (tid & 31) << 2;

    float4 acc[2][NT];
#pragma unroll
    for (int i = 0; i < 2; i++)
#pragma unroll
        for (int j = 0; j < NT; j++) acc[i][j] = make_float4(0.f, 0.f, 0.f, 0.f);

#pragma unroll
    for (int i = 0; i < 4; i++) {
        int m = am + i * 32;
        float4 v = make_float4(0.f, 0.f, 0.f, 0.f);
        if (m0 + m < M)
            v = *(const float4*)(A + (size_t)(m0 + m) * K + ak4);
        *(__half2*)&As[m][ak4]     = __floats2half2_rn(v.x, v.y);
        *(__half2*)&As[m][ak4 + 2] = __floats2half2_rn(v.z, v.w);
    }
#pragma unroll
    for (int i = 0; i < 4; i++) {
        int k = bk + i * 8;
        float4 v = *(const float4*)(B + (size_t)k * BN + bn4);
        *(__half2*)&Bs[k][bn4]     = __floats2half2_rn(v.x, v.y);
        *(__half2*)&Bs[k][bn4 + 2] = __floats2half2_rn(v.z, v.w);
    }
    __syncthreads();

    for (int k0 = 0; k0 < K; k0 += BK) {
        const bool has_next = (k0 + BK < K);
        float4 pa[4], pb[4];
        if (has_next) {
#pragma unroll
            for (int i = 0; i < 4; i++) {
                int m = am + i * 32;
                pa[i] = make_float4(0.f, 0.f, 0.f, 0.f);
                if (m0 + m < M)
                    pa[i] = *(const float4*)(A + (size_t)(m0 + m) * K + (k0 + BK) + ak4);
            }
#pragma unroll
            for (int i = 0; i < 4; i++) {
                int k = bk + i * 8;
                pb[i] = *(const float4*)(B + (size_t)(k0 + BK + k) * BN + bn4);
            }
        }

#pragma unroll
        for (int ks = 0; ks < 2; ks++) {
            const int c = ks * 16;
            uint32_t a[2][4];
#pragma unroll
            for (int mt = 0; mt < 2; mt++) {
                int r = warp_m * 32 + mt * 16 + qr;
                a[mt][0] = *(const uint32_t*)&As[r][c + 2 * qc];
                a[mt][1] = *(const uint32_t*)&As[r + 8][c + 2 * qc];
                a[mt][2] = *(const uint32_t*)&As[r][c + 2 * qc + 8];
                a[mt][3] = *(const uint32_t*)&As[r + 8][c + 2 * qc + 8];
            }
            uint32_t b[NT][2];
#pragma unroll
            for (int nt = 0; nt < NT; nt++) {
                int nn = warp_n * (NT * 8) + nt * 8 + qr;
                __half2 b0 = __halves2half2(Bs[c + 2 * qc][nn],     Bs[c + 2 * qc + 1][nn]);
                __half2 b1 = __halves2half2(Bs[c + 2 * qc + 8][nn], Bs[c + 2 * qc + 9][nn]);
                b[nt][0] = *(uint32_t*)&b0;
                b[nt][1] = *(uint32_t*)&b1;
            }
#pragma unroll
            for (int mt = 0; mt < 2; mt++)
#pragma unroll
                for (int nt = 0; nt < NT; nt++)
                    mma_f16(acc[mt][nt], a[mt][0], a[mt][1], a[mt][2], a[mt][3],
                            b[nt][0], b[nt][1]);
        }
        __syncthreads();

        if (has_next) {
#pragma unroll
            for (int i = 0; i < 4; i++) {
                int m = am + i * 32;
                *(__half2*)&As[m][ak4]     = __floats2half2_rn(pa[i].x, pa[i].y);
                *(__half2*)&As[m][ak4 + 2] = __floats2half2_rn(pa[i].z, pa[i].w);
            }
#pragma unroll
            for (int i = 0; i < 4; i++) {
                int k = bk + i * 8;
                *(__half2*)&Bs[k][bn4]     = __floats2half2_rn(pb[i].x, pb[i].y);
                *(__half2*)&Bs[k][bn4 + 2] = __floats2half2_rn(pb[i].z, pb[i].w);
            }
            __syncthreads();
        }
    }

#pragma unroll
    for (int mt = 0; mt < 2; mt++) {
        int row = m0 + warp_m * 32 + mt * 16 + qr;
#pragma unroll
        for (int nt = 0; nt < NT; nt++) {
            int col2 = (warp_n * (NT * 8) + nt * 8 + 2 * qc) >> 1;
            if (row < M)
                Ch[(size_t)row * (BN / 2) + col2] = __floats2half2_rn(acc[mt][nt].x, acc[mt][nt].y);
            if (row + 8 < M)
                Ch[(size_t)(row + 8) * (BN / 2) + col2] = __floats2half2_rn(acc[mt][nt].z, acc[mt][nt].w);
        }
    }
}

// ---------------- FUSED layer-1 agg + relu + GEMM2 ----------------------------
// Block: 256 threads, 128 nodes. Phase 1: warp w aggregates nodes w*16..w*16+15
// into smem o1 tile (fp16, relu'd). Phase 2: [128x128] @ W2[128x64] fp16 MMA.
// Dynamic smem: As = 128 x 136 halves (34816 B) — requires opt-in attribute
// (static Bs 18432 B pushes total past the 48KB default).
__global__ void __launch_bounds__(256) k_agg_gemm2(
    const int2* __restrict__ sc, const int* __restrict__ csr,
    const float* __restrict__ dinv, const __half2* __restrict__ h1,
    const float* __restrict__ bias1, const float* __restrict__ W2,
    __half2* __restrict__ h2h, int m_lo, int m_hi)
{
    constexpr int K = 128, BN = 64;
    constexpr int NT = BN / 16;              // 4 n8-tiles per warp
    constexpr int AS_PITCH = 136;            // halves per row (pad 8)
    extern __shared__ __half As[];           // [128][136]
    __shared__ __half Bs[K][BN + 8];

    const int tid    = threadIdx.x;
    const int warp   = tid >> 5;
    const int lane   = tid & 31;
    const int m0     = m_lo + blockIdx.x * 128;

    // ---- load W2 (128x64 fp32 -> fp16): 2048 float4, 8 per thread ----
#pragma unroll
    for (int it = 0; it < 8; it++) {
        int idx = tid + it * 256;
        int k  = idx >> 4;
        int n4 = (idx & 15) << 2;
        float4 v = *(const float4*)(W2 + (size_t)k * BN + n4);
        *(__half2*)&Bs[k][n4]     = __floats2half2_rn(v.x, v.y);
        *(__half2*)&Bs[k][n4 + 2] = __floats2half2_rn(v.z, v.w);
    }

    // ---- phase 1: aggregate 16 nodes per warp, write fp16 tile to smem ----
    float4 bv = *(const float4*)(bias1 + lane * 4);
    for (int i = 0; i < 16; i++) {
        int row = warp * 16 + i;
        int d = m0 + row;
        __half2 o0, o1;
        if (d < m_hi) {
            float dd = dinv[d];
            int2 scd = sc[d];
            int beg = scd.x, num = scd.y;
            uint2 raw = *(const uint2*)(h1 + (size_t)d * 64 + lane * 2);
            float2 p0 = __half22float2(*(__half2*)&raw.x);
            float2 p1 = __half22float2(*(__half2*)&raw.y);
            float sd = dd * dd;
            float4 acc;
            acc.x = fmaf(sd, p0.x, bv.x); acc.y = fmaf(sd, p0.y, bv.y);
            acc.z = fmaf(sd, p1.x, bv.z); acc.w = fmaf(sd, p1.y, bv.w);
#pragma unroll 4
            for (int j = 0; j < num; j++) {
                int s = __ldg(&csr[beg + j]);
                float nrm = dd * __ldg(&dinv[s]);
                uint2 r = *(const uint2*)(h1 + (size_t)s * 64 + lane * 2);
                float2 v0 = __half22float2(*(__half2*)&r.x);
                float2 v1 = __half22float2(*(__half2*)&r.y);
                acc.x = fmaf(nrm, v0.x, acc.x); acc.y = fmaf(nrm, v0.y, acc.y);
                acc.z = fmaf(nrm, v1.x, acc.z); acc.w = fmaf(nrm, v1.y, acc.w);
            }
            o0 = __floats2half2_rn(fmaxf(acc.x, 0.f), fmaxf(acc.y, 0.f));
            o1 = __floats2half2_rn(fmaxf(acc.z, 0.f), fmaxf(acc.w, 0.f));
        } else {
            o0 = __floats2half2_rn(0.f, 0.f);
            o1 = __floats2half2_rn(0.f, 0.f);
        }
        uint2 o;
        o.x = *(uint32_t*)&o0; o.y = *(uint32_t*)&o1;
        *(uint2*)&As[row * AS_PITCH + lane * 4] = o;
    }
    __syncthreads();

    // ---- phase 2: [128x128] @ [128x64] fp16 MMA, all K in smem ----
    const int warp_m = warp & 3;
    const int warp_n = warp >> 2;
    const int qr     = lane >> 2;
    const int qc     = lane & 3;

    float4 acc[2][NT];
#pragma unroll
    for (int i = 0; i < 2; i++)
#pragma unroll
        for (int j = 0; j < NT; j++) acc[i][j] = make_float4(0.f, 0.f, 0.f, 0.f);

#pragma unroll
    for (int ks = 0; ks < 8; ks++) {
        const int c = ks * 16;
        uint32_t a[2][4];
#pragma unroll
        for (int mt = 0; mt < 2; mt++) {
            int r = warp_m * 32 + mt * 16 + qr;
            a[mt][0] = *(const uint32_t*)&As[r * AS_PITCH + c + 2 * qc];
            a[mt][1] = *(const uint32_t*)&As[(r + 8) * AS_PITCH + c + 2 * qc];
            a[mt][2] = *(const uint32_t*)&As[r * AS_PITCH + c + 2 * qc + 8];
            a[mt][3] = *(const uint32_t*)&As[(r + 8) * AS_PITCH + c + 2 * qc + 8];
        }
        uint32_t b[NT][2];
#pragma unroll
        for (int nt = 0; nt < NT; nt++) {
            int nn = warp_n * (NT * 8) + nt * 8 + qr;
            __half2 b0 = __halves2half2(Bs[c + 2 * qc][nn],     Bs[c + 2 * qc + 1][nn]);
            __half2 b1 = __halves2half2(Bs[c + 2 * qc + 8][nn], Bs[c + 2 * qc + 9][nn]);
            b[nt][0] = *(uint32_t*)&b0;
            b[nt][1] = *(uint32_t*)&b1;
        }
#pragma unroll
        for (int mt = 0; mt < 2; mt++)
#pragma unroll
            for (int nt = 0; nt < NT; nt++)
                mma_f16(acc[mt][nt], a[mt][0], a[mt][1], a[mt][2], a[mt][3],
                        b[nt][0], b[nt][1]);
    }

#pragma unroll
    for (int mt = 0; mt < 2; mt++) {
        int row = m0 + warp_m * 32 + mt * 16 + qr;
#pragma unroll
        for (int nt = 0; nt < NT; nt++) {
            int col2 = (warp_n * (NT * 8) + nt * 8 + 2 * qc) >> 1;
            if (row < m_hi)
                h2h[(size_t)row * (BN / 2) + col2] = __floats2half2_rn(acc[mt][nt].x, acc[mt][nt].y);
            if (row + 8 < m_hi)
                h2h[(size_t)(row + 8) * (BN / 2) + col2] = __floats2half2_rn(acc[mt][nt].z, acc[mt][nt].w);
        }
    }
}

// ---------------- agg64: fp16 gather + fused final relu, fp32 out -------------
__global__ void __launch_bounds__(256) k_agg64_relu(
    const int2* __restrict__ sc, const int* __restrict__ csr,
    const float* __restrict__ dinv, const __half2* __restrict__ h,
    const float* __restrict__ bias, float* __restrict__ out, int n)
{
    int d = (blockIdx.x * blockDim.x + threadIdx.x) >> 5;
    int lane = threadIdx.x & 31;
    if (d >= n) return;
    float dd = dinv[d];
    int2 scd = sc[d];
    int beg = scd.x, num = scd.y;

    float2 hv = __half22float2(h[(size_t)d * 32 + lane]);
    float2 bv = *(const float2*)(bias + lane * 2);
    float sd = dd * dd;
    float2 acc;
    acc.x = fmaf(sd, hv.x, bv.x); acc.y = fmaf(sd, hv.y, bv.y);

#pragma unroll 4
    for (int j = 0; j < num; j++) {
        int s = __ldg(&csr[beg + j]);
        float nrm = dd * __ldg(&dinv[s]);
        float2 v = __half22float2(__ldg(h + (size_t)s * 32 + lane));
        acc.x = fmaf(nrm, v.x, acc.x); acc.y = fmaf(nrm, v.y, acc.y);
    }
    acc.x = fmaxf(acc.x, 0.f);
    acc.y = fmaxf(acc.y, 0.f);
    *(float2*)(out + (size_t)d * 64 + lane * 2) = acc;
}

// ==============================================================================
extern "C" void kernel_launch(void* const* d_in, const int* in_sizes, int n_in,
                              void* d_out, int out_size)
{
    const float* x    = (const float*)d_in[0];   // [N, 256]
    const int*   ei32 = (const int*)d_in[1];     // [2, E] int32 OR int64 (probed)
    const float* W1   = (const float*)d_in[2];   // [256, 128]
    const float* b1   = (const float*)d_in[3];   // [128]
    const float* W2   = (const float*)d_in[4];   // [128, 64]
    const float* b2   = (const float*)d_in[5];   // [64]
    float*       out  = (float*)d_out;           // [N, 64]

    const int n = in_sizes[0] / IN_CH;   // 50000
    const int e = in_sizes[1] / 2;       // 800000

    int *cnt, *rank, *csr;
    int2 *sc;
    float *dinv;
    __half2 *h1h, *h2h;
    cudaGetSymbolAddress((void**)&cnt,  g_cnt);
    cudaGetSymbolAddress((void**)&sc,   g_sc);
    cudaGetSymbolAddress((void**)&rank, g_rank);
    cudaGetSymbolAddress((void**)&csr,  g_csr_src);
    cudaGetSymbolAddress((void**)&dinv, g_dinv);
    cudaGetSymbolAddress((void**)&h1h,  g_h1h);
    cudaGetSymbolAddress((void**)&h2h,  g_h2h);

    const int SMEM_FUSED = 128 * 136 * (int)sizeof(__half);   // 34816 B dynamic

    // side stream + events + smem opt-in, once on the first (uncaptured) call
    static cudaStream_t s2 = nullptr;
    static cudaEvent_t  ev_fork = nullptr, ev_csr = nullptr,
                        ev_g1 = nullptr, ev_c1 = nullptr;
    if (s2 == nullptr) {
        cudaStreamCreateWithFlags(&s2, cudaStreamNonBlocking);
        cudaEventCreateWithFlags(&ev_fork, cudaEventDisableTiming);
        cudaEventCreateWithFlags(&ev_csr,  cudaEventDisableTiming);
        cudaEventCreateWithFlags(&ev_g1,   cudaEventDisableTiming);
        cudaEventCreateWithFlags(&ev_c1,   cudaEventDisableTiming);
        // static Bs (18432B) + dynamic As (34816B) > 48KB default: opt in
        cudaFuncSetAttribute(k_agg_gemm2,
                             cudaFuncAttributeMaxDynamicSharedMemorySize,
                             SMEM_FUSED);
    }

    const int T = 256;
    const int nb = (n + T - 1) / T;
    const int he = (e + 1) >> 1;
    const int eb2 = (he + T - 1) / T;
    const int half = ((n / 2) + 127) & ~127;

    // ---- fork: CSR build chain on s2, concurrent with GEMM1 on stream 0 ----
    cudaEventRecord(ev_fork, 0);
    cudaStreamWaitEvent(s2, ev_fork, 0);

    k_reset_detect <<<nb, T, 0, s2>>>(ei32, cnt, n, e, nb);
    k_hist_rank    <<<eb2, T, 0, s2>>>(ei32, cnt, rank, e);
    k_scan_lookback<<<nb, T, 0, s2>>>(cnt, sc, dinv, n);
    k_fill_rank    <<<eb2, T, 0, s2>>>(ei32, sc, rank, csr, e);
    cudaEventRecord(ev_csr, s2);

    // GEMM1 (fp16 MMA) on the main stream, overlapping the CSR build
    gemm1_f16<<<(n + 127) / 128, 256>>>(x, W1, h1h, n, IN_CH);
    cudaEventRecord(ev_g1, 0);

    // ---- chunked fused agg128+relu+GEMM2, two independent chains -----------
    cudaStreamWaitEvent(0, ev_csr, 0);
    k_agg_gemm2<<<half / 128, 256, SMEM_FUSED>>>(sc, csr, dinv, h1h, b1, W2, h2h, 0, half);

    cudaStreamWaitEvent(s2, ev_g1, 0);
    k_agg_gemm2<<<(n - half + 127) / 128, 256, SMEM_FUSED, s2>>>(sc, csr, dinv, h1h, b1, W2, h2h, half, n);
    cudaEventRecord(ev_c1, s2);

    // ---- join: agg64 needs the full h2 ----
    cudaStreamWaitEvent(0, ev_c1, 0);
    k_agg64_relu<<<(n * 32 + T - 1) / T, T>>>(sc, csr, dinv, h2h, b2, out, n);
}